// round 13
// baseline (speedup 1.0000x reference)
#include <cuda_runtime.h>
#include <cuda_bf16.h>
#include <math_constants.h>

// ----------------------------------------------------------------------------
// MinArcSoftmaxLoss — lean stats kernel + streaming kernel with fused finalize.
//   theta = acos(costh); pos = theta[r,label]; mean/std (ddof=1)
//   d = mean + std*eps (0 at label); mm = cos(theta-d); pm = cos(theta+M@label)
//   logits = S*(A*mm + pm)/(1+A); loss = -mean(log_softmax[label])
// Streaming math (3 MUFU/elem — measured best): theta = poly-acos(c) (sqrt),
// mm = cos(theta-d) (cos), exp via ex2.
// Load schedule sweep: MLP_p1 2 (69.6us) < 4 (68.4us, regs 32) > 8 (76.5us,
// regs 38, occupancy cliff). This round probes the midpoint: MLP_p1 = 6
// (3-way batching; expected regs ~35, ~7 blocks/SM).
// NSPLIT=4 confirmed (8 was worse). Fixed softmax shift of 64.
// Finalize runs in the LAST streaming block (done-counter, reset for replay).
// ----------------------------------------------------------------------------

#define BQ      512
#define NSPLIT  4
#define GRID    (BQ * NSPLIT)       // 2048 blocks, 25000 elems each
#define NTHR    256

__device__ unsigned g_done = 0;
__device__ float g_mean, g_std;
__device__ float g_fix[BQ];         // pr - pw per row
__device__ float g_logit[BQ];       // correct label logit per row
__device__ float g_partial[GRID];

#define K1F   ((float)(64.0 * 0.1 / 1.1))                      // S*A/(1+A)
#define K2F   ((float)(64.0 / 1.1))                            // S/(1+A)
#define L1F   ((float)(64.0 * 0.1 / 1.1 * 1.4426950408889634)) // K1*log2(e)
#define L2F   ((float)(64.0 / 1.1 * 1.4426950408889634))       // K2*log2(e)
#define LOG2E 1.4426950408889634f
#define BIASF ((float)(64.0 * 1.4426950408889634))             // 64*log2(e)
#define COSM  0.8775825618903728f                              // cos(0.5)
#define SINM  0.479425538604203f                               // sin(0.5)

__device__ __forceinline__ float fast_cos(float x) {
    float r; asm("cos.approx.ftz.f32 %0, %1;" : "=f"(r) : "f"(x)); return r;
}
__device__ __forceinline__ float fast_ex2(float x) {
    float r; asm("ex2.approx.ftz.f32 %0, %1;" : "=f"(r) : "f"(x)); return r;
}
__device__ __forceinline__ float fast_sqrt(float x) {
    float r; asm("sqrt.approx.ftz.f32 %0, %1;" : "=f"(r) : "f"(x)); return r;
}

// acos via Hastings poly, abs err ~6.8e-5 (fine vs 1e-3 tolerance)
__device__ __forceinline__ float facos(float x) {
    float u = fabsf(x);
    float t = fast_sqrt(1.0f - u);
    float p = fmaf(u, fmaf(u, fmaf(u, -0.0187292994f, 0.0742610037f),
                           -0.2121144025f), 1.5707288f);
    p *= t;
    return (x >= 0.0f) ? p : ((float)M_PI - p);
}

// exp(logit - 64) via the off-label formula (identical in stream + fixup).
// 3 MUFU: sqrt (inside facos), cos, ex2.
__device__ __forceinline__ float term(float c, float e, float mean, float stdv) {
    float theta = facos(c);
    float x  = fmaf(-e, stdv, theta - mean);   // theta - d
    float mm = fast_cos(x);                    // cos(theta - d)
    return fast_ex2(fmaf(L1F, mm, fmaf(L2F, c, -BIASF)));
}

__device__ __forceinline__ float term4(float4 c, float4 e, float mean, float stdv) {
    return term(c.x, e.x, mean, stdv) + term(c.y, e.y, mean, stdv)
         + term(c.z, e.z, mean, stdv) + term(c.w, e.w, mean, stdv);
}

// sum over 512 threads via shuffles + one smem pass; result broadcast via smem
__device__ __forceinline__ float blockSum512(float v, volatile float* sh16) {
    #pragma unroll
    for (int o = 16; o; o >>= 1) v += __shfl_down_sync(0xffffffffu, v, o);
    if ((threadIdx.x & 31) == 0) sh16[threadIdx.x >> 5] = v;
    __syncthreads();
    if (threadIdx.x < 32) {
        float x = (threadIdx.x < 16) ? sh16[threadIdx.x] : 0.0f;
        #pragma unroll
        for (int o = 8; o; o >>= 1) x += __shfl_down_sync(0xffffffffu, x, o);
        if (threadIdx.x == 0) sh16[0] = x;
    }
    __syncthreads();
    float r = sh16[0];
    __syncthreads();
    return r;
}

// ---------------- kernel 1: dtype detect + mean/std + per-row fixup ---------
__global__ void __launch_bounds__(BQ) stats_kernel(const float* __restrict__ costh,
                                                   const float* __restrict__ eps,
                                                   const int* __restrict__ lab32,
                                                   int C) {
    __shared__ float sh16[16];
    int r = threadIdx.x;
    // dtype detect: int64 labels (<1e5) have all-zero odd int32 slots
    int odd = lab32[2 * r + 1];
    int any = __syncthreads_or(odd);
    int lab = (any == 0) ? lab32[2 * r] : lab32[r];
    size_t idx = (size_t)r * C + (size_t)lab;
    float cl = __ldg(costh + idx);
    float el = __ldg(eps + idx);

    float theta = facos(cl);
    float mean = blockSum512(theta, sh16) * (1.0f / (float)BQ);
    float dev = theta - mean;
    float var = blockSum512(dev * dev, sh16) * (1.0f / (float)(BQ - 1));
    float stdv = sqrtf(var);

    // per-row fixup: remove wrong-formula term, add correct label term
    float pw = term(cl, el, mean, stdv);
    float s2 = fmaf(-cl, cl, 1.0f);
    float sl = sqrtf(s2);
    float logit_r = fmaf(K1F, cl, K2F * fmaf(cl, COSM, -sl * SINM));
    float pr = fast_ex2(fmaf(logit_r, LOG2E, -BIASF));
    g_fix[r]   = pr - pw;
    g_logit[r] = logit_r;
    if (r == 0) { g_mean = mean; g_std = stdv; }
}

// ---------------- kernel 2: streaming exp-sums + fused finalize --------------
__global__ void __launch_bounds__(NTHR) main_kernel(const float* __restrict__ costh,
                                                    const float* __restrict__ eps,
                                                    float* __restrict__ out,
                                                    int C) {
    __shared__ float sh[8];
    int tid = threadIdx.x;
    int row   = blockIdx.x >> 2;
    int split = blockIdx.x & 3;
    int chunk = C / NSPLIT;                  // 25000 (%4 == 0)
    int nvec  = chunk >> 2;                  // 6250 float4s
    size_t base = (size_t)row * C + (size_t)split * chunk;
    const float4* __restrict__ c4 = (const float4*)(costh + base);
    const float4* __restrict__ e4 = (const float4*)(eps + base);

    float mean = g_mean, stdv = g_std;
    float acc = 0.0f;

    // 3-way batched loop: 6 front-batched LDG.128 per iteration (MLP_p1 = 6)
    int i = tid;
    for (; i + 2 * NTHR < nvec; i += 3 * NTHR) {
        float4 ca = c4[i];
        float4 cb = c4[i + NTHR];
        float4 cc = c4[i + 2 * NTHR];
        float4 ea = e4[i];
        float4 eb = e4[i + NTHR];
        float4 ec = e4[i + 2 * NTHR];
        acc += term4(ca, ea, mean, stdv);
        acc += term4(cb, eb, mean, stdv);
        acc += term4(cc, ec, mean, stdv);
    }
    for (; i < nvec; i += NTHR) {
        float4 c = c4[i];
        float4 e = e4[i];
        acc += term4(c, e, mean, stdv);
    }

    #pragma unroll
    for (int o = 16; o; o >>= 1) acc += __shfl_down_sync(0xffffffffu, acc, o);
    if ((tid & 31) == 0) sh[tid >> 5] = acc;
    __syncthreads();
    if (tid < 32) {
        float v = (tid < 8) ? sh[tid] : 0.0f;
        #pragma unroll
        for (int o = 4; o; o >>= 1) v += __shfl_down_sync(0xffffffffu, v, o);
        if (tid == 0) sh[0] = v;
    }
    __syncthreads();

    // publish partial, then count completion
    __shared__ bool s_last;
    if (tid == 0) {
        g_partial[blockIdx.x] = sh[0];
        __threadfence();
        unsigned d = atomicAdd(&g_done, 1u);
        s_last = (d == GRID - 1u);
    }
    __syncthreads();
    if (!s_last) return;

    // -------- fused finalize (last block only) --------
    __threadfence();                         // acquire all partials/fixups
    float lsum = 0.0f;
    for (int r = tid; r < BQ; r += NTHR) {
        float s = 0.0f;
        #pragma unroll
        for (int j = 0; j < NSPLIT; j++) s += __ldcg(&g_partial[r * NSPLIT + j]);
        s += __ldcg(&g_fix[r]);
        lsum += 64.0f + logf(s) - __ldcg(&g_logit[r]);   // -logp[label]
    }
    #pragma unroll
    for (int o = 16; o; o >>= 1) lsum += __shfl_down_sync(0xffffffffu, lsum, o);
    if ((tid & 31) == 0) sh[tid >> 5] = lsum;
    __syncthreads();
    if (tid < 32) {
        float v = (tid < 8) ? sh[tid] : 0.0f;
        #pragma unroll
        for (int o = 4; o; o >>= 1) v += __shfl_down_sync(0xffffffffu, v, o);
        if (tid == 0) {
            out[0] = v / (float)BQ;
            g_done = 0;                      // fresh counter for next replay
        }
    }
}

// ----------------------------------------------------------------------------
extern "C" void kernel_launch(void* const* d_in, const int* in_sizes, int n_in,
                              void* d_out, int out_size) {
    const float* costh = (const float*)d_in[0];
    const float* eps   = (const float*)d_in[1];
    const int*   lab32 = (const int*)d_in[2];
    int C = in_sizes[0] / BQ;        // 100000

    stats_kernel<<<1, BQ>>>(costh, eps, lab32, C);
    main_kernel<<<GRID, NTHR>>>(costh, eps, (float*)d_out, C);
}

// round 14
// speedup vs baseline: 1.2492x; 1.2492x over previous
#include <cuda_runtime.h>
#include <cuda_bf16.h>
#include <math_constants.h>

// ----------------------------------------------------------------------------
// MinArcSoftmaxLoss — lean stats kernel + streaming kernel with fused finalize.
//   theta = acos(costh); pos = theta[r,label]; mean/std (ddof=1)
//   d = mean + std*eps (0 at label); mm = cos(theta-d); pm = cos(theta+M@label)
//   logits = S*(A*mm + pm)/(1+A); loss = -mean(log_softmax[label])
// CONVERGED CONFIGURATION (round-10 measured optimum, 70.4us):
//   * math: 3 MUFU/elem — poly-acos (sqrt) + cos.approx + ex2.
//     (4-MUFU, 2-MUFU, and FMA-pipe-cos variants all measured slower.)
//   * loads: pair-batched float4, MLP_p1 = 4 — the largest front batch that
//     compiles to exactly 32 regs / 8 blocks/SM. MLP 2/6/8 all slower
//     (6 and 8 fall off the 32-reg occupancy cliff).
//   * NSPLIT = 4 (2048 blocks x 25000 elems; 8/25-way splits slower).
//   * serial stats launch (PDL and persistent variants slower).
//   * finalize fused into the last streaming block via done-counter.
// Fixed softmax shift of 64 (>= all logits, provably safe).
// ----------------------------------------------------------------------------

#define BQ      512
#define NSPLIT  4
#define GRID    (BQ * NSPLIT)       // 2048 blocks, 25000 elems each
#define NTHR    256

__device__ unsigned g_done = 0;
__device__ float g_mean, g_std;
__device__ float g_fix[BQ];         // pr - pw per row
__device__ float g_logit[BQ];       // correct label logit per row
__device__ float g_partial[GRID];

#define K1F   ((float)(64.0 * 0.1 / 1.1))                      // S*A/(1+A)
#define K2F   ((float)(64.0 / 1.1))                            // S/(1+A)
#define L1F   ((float)(64.0 * 0.1 / 1.1 * 1.4426950408889634)) // K1*log2(e)
#define L2F   ((float)(64.0 / 1.1 * 1.4426950408889634))       // K2*log2(e)
#define LOG2E 1.4426950408889634f
#define BIASF ((float)(64.0 * 1.4426950408889634))             // 64*log2(e)
#define COSM  0.8775825618903728f                              // cos(0.5)
#define SINM  0.479425538604203f                               // sin(0.5)

__device__ __forceinline__ float fast_cos(float x) {
    float r; asm("cos.approx.ftz.f32 %0, %1;" : "=f"(r) : "f"(x)); return r;
}
__device__ __forceinline__ float fast_ex2(float x) {
    float r; asm("ex2.approx.ftz.f32 %0, %1;" : "=f"(r) : "f"(x)); return r;
}
__device__ __forceinline__ float fast_sqrt(float x) {
    float r; asm("sqrt.approx.ftz.f32 %0, %1;" : "=f"(r) : "f"(x)); return r;
}

// acos via Hastings poly, abs err ~6.8e-5 (fine vs 1e-3 tolerance)
__device__ __forceinline__ float facos(float x) {
    float u = fabsf(x);
    float t = fast_sqrt(1.0f - u);
    float p = fmaf(u, fmaf(u, fmaf(u, -0.0187292994f, 0.0742610037f),
                           -0.2121144025f), 1.5707288f);
    p *= t;
    return (x >= 0.0f) ? p : ((float)M_PI - p);
}

// exp(logit - 64) via the off-label formula (identical in stream + fixup).
// 3 MUFU: sqrt (inside facos), cos, ex2.
__device__ __forceinline__ float term(float c, float e, float mean, float stdv) {
    float theta = facos(c);
    float x  = fmaf(-e, stdv, theta - mean);   // theta - d
    float mm = fast_cos(x);                    // cos(theta - d)
    return fast_ex2(fmaf(L1F, mm, fmaf(L2F, c, -BIASF)));
}

__device__ __forceinline__ float term4(float4 c, float4 e, float mean, float stdv) {
    return term(c.x, e.x, mean, stdv) + term(c.y, e.y, mean, stdv)
         + term(c.z, e.z, mean, stdv) + term(c.w, e.w, mean, stdv);
}

// sum over 512 threads via shuffles + one smem pass; result broadcast via smem
__device__ __forceinline__ float blockSum512(float v, volatile float* sh16) {
    #pragma unroll
    for (int o = 16; o; o >>= 1) v += __shfl_down_sync(0xffffffffu, v, o);
    if ((threadIdx.x & 31) == 0) sh16[threadIdx.x >> 5] = v;
    __syncthreads();
    if (threadIdx.x < 32) {
        float x = (threadIdx.x < 16) ? sh16[threadIdx.x] : 0.0f;
        #pragma unroll
        for (int o = 8; o; o >>= 1) x += __shfl_down_sync(0xffffffffu, x, o);
        if (threadIdx.x == 0) sh16[0] = x;
    }
    __syncthreads();
    float r = sh16[0];
    __syncthreads();
    return r;
}

// ---------------- kernel 1: dtype detect + mean/std + per-row fixup ---------
__global__ void __launch_bounds__(BQ) stats_kernel(const float* __restrict__ costh,
                                                   const float* __restrict__ eps,
                                                   const int* __restrict__ lab32,
                                                   int C) {
    __shared__ float sh16[16];
    int r = threadIdx.x;
    // dtype detect: int64 labels (<1e5) have all-zero odd int32 slots
    int odd = lab32[2 * r + 1];
    int any = __syncthreads_or(odd);
    int lab = (any == 0) ? lab32[2 * r] : lab32[r];
    size_t idx = (size_t)r * C + (size_t)lab;
    float cl = __ldg(costh + idx);
    float el = __ldg(eps + idx);

    float theta = facos(cl);
    float mean = blockSum512(theta, sh16) * (1.0f / (float)BQ);
    float dev = theta - mean;
    float var = blockSum512(dev * dev, sh16) * (1.0f / (float)(BQ - 1));
    float stdv = sqrtf(var);

    // per-row fixup: remove wrong-formula term, add correct label term
    float pw = term(cl, el, mean, stdv);
    float s2 = fmaf(-cl, cl, 1.0f);
    float sl = sqrtf(s2);
    float logit_r = fmaf(K1F, cl, K2F * fmaf(cl, COSM, -sl * SINM));
    float pr = fast_ex2(fmaf(logit_r, LOG2E, -BIASF));
    g_fix[r]   = pr - pw;
    g_logit[r] = logit_r;
    if (r == 0) { g_mean = mean; g_std = stdv; }
}

// ---------------- kernel 2: streaming exp-sums + fused finalize --------------
__global__ void __launch_bounds__(NTHR) main_kernel(const float* __restrict__ costh,
                                                    const float* __restrict__ eps,
                                                    float* __restrict__ out,
                                                    int C) {
    __shared__ float sh[8];
    int tid = threadIdx.x;
    int row   = blockIdx.x >> 2;
    int split = blockIdx.x & 3;
    int chunk = C / NSPLIT;                  // 25000 (%4 == 0)
    int nvec  = chunk >> 2;                  // 6250 float4s
    size_t base = (size_t)row * C + (size_t)split * chunk;
    const float4* __restrict__ c4 = (const float4*)(costh + base);
    const float4* __restrict__ e4 = (const float4*)(eps + base);

    float mean = g_mean, stdv = g_std;
    float acc = 0.0f;

    // pair-batched loop: 4 front-batched LDG.128 per iteration (MLP_p1 = 4)
    int i = tid;
    for (; i + NTHR < nvec; i += 2 * NTHR) {
        float4 ca = c4[i];
        float4 cb = c4[i + NTHR];
        float4 ea = e4[i];
        float4 eb = e4[i + NTHR];
        acc += term4(ca, ea, mean, stdv);
        acc += term4(cb, eb, mean, stdv);
    }
    if (i < nvec) {
        float4 c = c4[i];
        float4 e = e4[i];
        acc += term4(c, e, mean, stdv);
    }

    #pragma unroll
    for (int o = 16; o; o >>= 1) acc += __shfl_down_sync(0xffffffffu, acc, o);
    if ((tid & 31) == 0) sh[tid >> 5] = acc;
    __syncthreads();
    if (tid < 32) {
        float v = (tid < 8) ? sh[tid] : 0.0f;
        #pragma unroll
        for (int o = 4; o; o >>= 1) v += __shfl_down_sync(0xffffffffu, v, o);
        if (tid == 0) sh[0] = v;
    }
    __syncthreads();

    // publish partial, then count completion
    __shared__ bool s_last;
    if (tid == 0) {
        g_partial[blockIdx.x] = sh[0];
        __threadfence();
        unsigned d = atomicAdd(&g_done, 1u);
        s_last = (d == GRID - 1u);
    }
    __syncthreads();
    if (!s_last) return;

    // -------- fused finalize (last block only) --------
    __threadfence();                         // acquire all partials/fixups
    float lsum = 0.0f;
    for (int r = tid; r < BQ; r += NTHR) {
        float s = 0.0f;
        #pragma unroll
        for (int j = 0; j < NSPLIT; j++) s += __ldcg(&g_partial[r * NSPLIT + j]);
        s += __ldcg(&g_fix[r]);
        lsum += 64.0f + logf(s) - __ldcg(&g_logit[r]);   // -logp[label]
    }
    #pragma unroll
    for (int o = 16; o; o >>= 1) lsum += __shfl_down_sync(0xffffffffu, lsum, o);
    if ((tid & 31) == 0) sh[tid >> 5] = lsum;
    __syncthreads();
    if (tid < 32) {
        float v = (tid < 8) ? sh[tid] : 0.0f;
        #pragma unroll
        for (int o = 4; o; o >>= 1) v += __shfl_down_sync(0xffffffffu, v, o);
        if (tid == 0) {
            out[0] = v / (float)BQ;
            g_done = 0;                      // fresh counter for next replay
        }
    }
}

// ----------------------------------------------------------------------------
extern "C" void kernel_launch(void* const* d_in, const int* in_sizes, int n_in,
                              void* d_out, int out_size) {
    const float* costh = (const float*)d_in[0];
    const float* eps   = (const float*)d_in[1];
    const int*   lab32 = (const int*)d_in[2];
    int C = in_sizes[0] / BQ;        // 100000

    stats_kernel<<<1, BQ>>>(costh, eps, lab32, C);
    main_kernel<<<GRID, NTHR>>>(costh, eps, (float*)d_out, C);
}